// round 5
// baseline (speedup 1.0000x reference)
#include <cuda_runtime.h>
#include <cuda_bf16.h>
#include <cstdint>

// ---------------- hash-grid constants (precomputed from reference config) ----
__constant__ float c_scale[16] = {
    15.0f,          21.1106061f,   29.5549331f,   41.2242532f,
    57.3502375f,    79.6349472f,  110.4304720f,  152.9872000f,
    211.7969070f,  293.0667790f,  405.3746690f,  560.5743900f,
    775.0469010f, 1071.4291820f, 1481.0036600f, 2047.0f
};
__constant__ uint32_t c_res1[5] = {17u, 24u, 32u, 44u, 60u};
__constant__ int c_offset[16] = {
    0, 4920, 18744, 51512, 136696, 352696, 876984, 1401272,
    1925560, 2449848, 2974136, 3498424, 4022712, 4547000, 5071288, 5595576
};

#define NPTS 524288

// scratch (allocation-free rule: __device__ globals)
__device__ __nv_bfloat16 g_featb[(size_t)NPTS * 32];
__device__ __nv_bfloat16 g_w1b[32 * 256];
__device__ __nv_bfloat16 g_w2b[256 * 256];
__device__ __nv_bfloat16 g_w3b[256 * 256];

// ------------------------------------------------------- weight conversion --
__global__ void cvtw_kernel(const float* __restrict__ w1,
                            const float* __restrict__ w2,
                            const float* __restrict__ w3,
                            __nv_bfloat16* __restrict__ o1,
                            __nv_bfloat16* __restrict__ o2,
                            __nv_bfloat16* __restrict__ o3) {
    int i = blockIdx.x * 256 + threadIdx.x;   // grid covers 65536
    if (i < 32 * 256) o1[i] = __float2bfloat16(w1[i]);
    o2[i] = __float2bfloat16(w2[i]);
    o3[i] = __float2bfloat16(w3[i]);
}

// ---------------------------------------------------------------- encode ----
// 2 threads per point: thread handles 8 levels (h=0 -> 0..7, h=1 -> 8..15)
__global__ void encode_kernel(const float* __restrict__ x,
                              const float* __restrict__ table,
                              __nv_bfloat16* __restrict__ featb, int N) {
    int t = blockIdx.x * blockDim.x + threadIdx.x;
    int i = t >> 1;
    int h = t & 1;
    if (i >= N) return;

    float x0 = x[3 * i + 0] * (1.0f / 1.5f);
    float x1 = x[3 * i + 1] * (1.0f / 1.5f);
    float x2 = x[3 * i + 2] * (1.0f / 1.5f);

    __nv_bfloat162* f2 = (__nv_bfloat162*)featb;

    #pragma unroll
    for (int li = 0; li < 8; li++) {
        const int l = h * 8 + li;
        float s = c_scale[l];
        float px = x0 * s + 0.5f;
        float py = x1 * s + 0.5f;
        float pz = x2 * s + 0.5f;
        float fx = floorf(px), fy = floorf(py), fz = floorf(pz);
        float tx = px - fx, ty = py - fy, tz = pz - fz;
        uint32_t X = (uint32_t)fx, Y = (uint32_t)fy, Z = (uint32_t)fz;
        float wx[2] = {1.0f - tx, tx};
        float wy[2] = {1.0f - ty, ty};
        float wz[2] = {1.0f - tz, tz};

        float a0 = 0.0f, a1 = 0.0f;
        #pragma unroll
        for (int c = 0; c < 8; c++) {
            uint32_t bx = (uint32_t)(c & 1);
            uint32_t by = (uint32_t)((c >> 1) & 1);
            uint32_t bz = (uint32_t)((c >> 2) & 1);
            uint32_t cx = X + bx, cy = Y + by, cz = Z + bz;
            uint32_t idx;
            if (h == 0 && li < 5) {
                uint32_t r1 = c_res1[li];
                idx = cx + cy * r1 + cz * r1 * r1;   // dense
            } else {
                idx = (cx * 1u ^ cy * 2654435761u ^ cz * 805459861u) & 524287u;
            }
            float w = wx[bx] * wy[by] * wz[bz];
            float2 t2 = __ldg((const float2*)table + (c_offset[l] + (int)idx));
            a0 += w * t2.x;
            a1 += w * t2.y;
        }
        f2[(size_t)i * 16 + l] = __float22bfloat162_rn(make_float2(a0, a1));
    }
}

// ------------------------------------------------------------ MMA helpers ---
__device__ __forceinline__ uint32_t scvta(const void* p) {
    return (uint32_t)__cvta_generic_to_shared(p);
}
__device__ __forceinline__ void ldsm_x4(uint32_t* r, uint32_t addr) {
    asm volatile("ldmatrix.sync.aligned.m8n8.x4.shared.b16 {%0,%1,%2,%3}, [%4];"
                 : "=r"(r[0]), "=r"(r[1]), "=r"(r[2]), "=r"(r[3]) : "r"(addr));
}
__device__ __forceinline__ void ldsm_x4_t(uint32_t* r, uint32_t addr) {
    asm volatile("ldmatrix.sync.aligned.m8n8.x4.trans.shared.b16 {%0,%1,%2,%3}, [%4];"
                 : "=r"(r[0]), "=r"(r[1]), "=r"(r[2]), "=r"(r[3]) : "r"(addr));
}
__device__ __forceinline__ void mma_bf16(float* c, const uint32_t* a, const uint32_t* b) {
    asm volatile("mma.sync.aligned.m16n8k16.row.col.f32.bf16.bf16.f32 "
                 "{%0,%1,%2,%3}, {%4,%5,%6,%7}, {%8,%9}, {%0,%1,%2,%3};"
                 : "+f"(c[0]), "+f"(c[1]), "+f"(c[2]), "+f"(c[3])
                 : "r"(a[0]), "r"(a[1]), "r"(a[2]), "r"(a[3]),
                   "r"(b[0]), "r"(b[1]));
}
__device__ __forceinline__ void cp16(void* smem, const void* gmem) {
    asm volatile("cp.async.cg.shared.global [%0], [%1], 16;"
                 :: "r"(scvta(smem)), "l"(gmem));
}
__device__ __forceinline__ void cp_commit() {
    asm volatile("cp.async.commit_group;");
}
template <int NG>
__device__ __forceinline__ void cp_wait() {
    asm volatile("cp.async.wait_group %0;" :: "n"(NG));
}

// SMEM layout (elements of bf16): A0 | A1 | Wbuf0 | Wbuf1 | bias(float)
#define SA  264     // A row stride (bf16), 528 B -> conflict-free ldmatrix
#define SWS 136     // W row stride (bf16), 272 B -> conflict-free ldmatrix
#define A_ELEMS (128 * SA)            // 33792
#define WCH_ELEMS (64 * SWS)          // 8704 (one 64-row chunk buffer)
#define SMEM_BYTES ((2 * A_ELEMS + 2 * WCH_ELEMS) * 2 + 128 * 4)   // 170496

// issue cp.async for one W chunk: rows [kBase, kBase+CROWS) cols [colBase,+128)
template <int CROWS>
__device__ __forceinline__ void issue_w_chunk(__nv_bfloat16* dst,
                                              const __nv_bfloat16* __restrict__ Wg,
                                              int kBase, int colBase, int tid) {
    #pragma unroll
    for (int v = tid; v < CROWS * 16; v += 256) {
        int r = v >> 4, seg = (v & 15) * 8;
        cp16(dst + r * SWS + seg,
             Wg + (size_t)(kBase + r) * 256 + colBase + seg);
    }
    cp_commit();
}

// One layer: sOut[128,256] = relu(sIn[128,K] @ W[K,256] + bias), bf16 in/out.
// 8 warps: warp tile 32 rows x 64 cols; 2 column passes of 128.
// W streamed in 64-row chunks, double-buffered via cp.async.
template <int K>
__device__ __forceinline__ void layer(const __nv_bfloat16* __restrict__ Wg,
                                      const float* __restrict__ bias,
                                      const __nv_bfloat16* sIn,
                                      __nv_bfloat16* sOut,
                                      __nv_bfloat16* sW0, __nv_bfloat16* sW1,
                                      float* sBias) {
    constexpr int CH  = (K >= 64) ? 64 : K;   // chunk rows
    constexpr int NCH = K / CH;               // chunks per pass

    const int tid  = threadIdx.x;
    const int lane = tid & 31;
    const int wid  = tid >> 5;
    const int m0   = (wid & 3) * 32;
    const int n0   = (wid >> 2) * 64;
    const int lr   = lane & 15;
    const int lc   = (lane >> 4) << 3;
    __nv_bfloat16* sWb[2] = {sW0, sW1};

    #pragma unroll
    for (int pass = 0; pass < 2; pass++) {
        const int colBase = pass * 128;
        __syncthreads();   // sIn ready / W buffers + sBias free

        if (K == 32) {
            // both passes' chunks fit in the two buffers; issue both at pass 0
            if (pass == 0) {
                issue_w_chunk<CH>(sW0, Wg, 0, 0, tid);
                issue_w_chunk<CH>(sW1, Wg, 0, 128, tid);
            }
        } else {
            issue_w_chunk<CH>(sW0, Wg, 0, colBase, tid);
            if (NCH > 1) issue_w_chunk<CH>(sW1, Wg, CH, colBase, tid);
        }
        if (tid < 128) sBias[tid] = bias[colBase + tid];

        float acc[2][8][4];
        #pragma unroll
        for (int mi = 0; mi < 2; mi++)
            #pragma unroll
            for (int nj = 0; nj < 8; nj++)
                #pragma unroll
                for (int q = 0; q < 4; q++) acc[mi][nj][q] = 0.0f;

        #pragma unroll
        for (int c = 0; c < NCH; c++) {
            // wait for chunk c's group (groups retire in order)
            if (K == 32) {
                if (pass == 0) cp_wait<1>(); else cp_wait<0>();
            } else {
                if (c < NCH - 1) cp_wait<1>(); else cp_wait<0>();
            }
            __syncthreads();

            const __nv_bfloat16* sW = (K == 32) ? sWb[pass] : sWb[c & 1];
            #pragma unroll
            for (int k0 = 0; k0 < CH; k0 += 16) {
                const int kg = c * CH + k0;   // global k for A
                uint32_t afr[2][4];
                #pragma unroll
                for (int mi = 0; mi < 2; mi++)
                    ldsm_x4(afr[mi], scvta(sIn + (m0 + mi * 16 + lr) * SA + kg + lc));
                uint32_t bfr[8][2];
                #pragma unroll
                for (int nq = 0; nq < 4; nq++) {
                    uint32_t r[4];
                    ldsm_x4_t(r, scvta(sW + (k0 + lr) * SWS + n0 + nq * 16 + lc));
                    bfr[nq * 2 + 0][0] = r[0]; bfr[nq * 2 + 0][1] = r[1];
                    bfr[nq * 2 + 1][0] = r[2]; bfr[nq * 2 + 1][1] = r[3];
                }
                #pragma unroll
                for (int mi = 0; mi < 2; mi++)
                    #pragma unroll
                    for (int nj = 0; nj < 8; nj++)
                        mma_bf16(acc[mi][nj], afr[mi], bfr[nj]);
            }

            // prefetch chunk c+2 into the buffer we just finished reading
            if (K != 32 && c + 2 < NCH) {
                __syncthreads();   // all warps done reading sWb[c&1]
                issue_w_chunk<CH>(sWb[c & 1], Wg, (c + 2) * CH, colBase, tid);
            }
        }

        // bias + relu + store bf16x2
        #pragma unroll
        for (int mi = 0; mi < 2; mi++) {
            #pragma unroll
            for (int nj = 0; nj < 8; nj++) {
                int colL = n0 + nj * 8 + (lane & 3) * 2;
                float b0v = sBias[colL], b1v = sBias[colL + 1];
                int row = m0 + mi * 16 + (lane >> 2);
                float v0 = fmaxf(acc[mi][nj][0] + b0v, 0.0f);
                float v1 = fmaxf(acc[mi][nj][1] + b1v, 0.0f);
                *(__nv_bfloat162*)(sOut + row * SA + colBase + colL) =
                    __float22bfloat162_rn(make_float2(v0, v1));
                float v2 = fmaxf(acc[mi][nj][2] + b0v, 0.0f);
                float v3 = fmaxf(acc[mi][nj][3] + b1v, 0.0f);
                *(__nv_bfloat162*)(sOut + (row + 8) * SA + colBase + colL) =
                    __float22bfloat162_rn(make_float2(v2, v3));
            }
        }
    }
}

// -------------------------------------------------- fully-fused MLP kernel --
__global__ void __launch_bounds__(256, 1)
fused_mlp(const __nv_bfloat16* __restrict__ feat,
          const __nv_bfloat16* __restrict__ w1b,
          const __nv_bfloat16* __restrict__ w2b,
          const __nv_bfloat16* __restrict__ w3b,
          const float* __restrict__ b1, const float* __restrict__ b2,
          const float* __restrict__ b3, const float* __restrict__ w4,
          const float* __restrict__ b4, float* __restrict__ out, int N) {
    extern __shared__ __nv_bfloat16 smem_bf[];
    __nv_bfloat16* sA0 = smem_bf;
    __nv_bfloat16* sA1 = smem_bf + A_ELEMS;
    __nv_bfloat16* sW0 = smem_bf + 2 * A_ELEMS;
    __nv_bfloat16* sW1 = sW0 + WCH_ELEMS;
    float* sBias = (float*)(sW1 + WCH_ELEMS);

    const int tid = threadIdx.x;
    const int rowBase = blockIdx.x * 128;

    // async-load feat tile [128,32] bf16 -> sA0 (group 0)
    #pragma unroll
    for (int v = tid; v < 512; v += 256) {
        int row = v >> 2, j = v & 3;
        int gr = min(rowBase + row, N - 1);
        cp16(sA0 + row * SA + j * 8, feat + (size_t)gr * 32 + j * 8);
    }
    cp_commit();

    layer<32>(w1b, b1, sA0, sA1, sW0, sW1, sBias);
    layer<256>(w2b, b2, sA1, sA0, sW0, sW1, sBias);
    layer<256>(w3b, b3, sA0, sA1, sW0, sW1, sBias);

    __syncthreads();
    float* sW4 = (float*)sW0;   // 768 w4 + 3 b4
    for (int v = tid; v < 768; v += 256) sW4[v] = w4[v];
    if (tid < 3) sW4[768 + tid] = b4[tid];
    __syncthreads();

    if (tid < 128) {
        int row = tid;
        int gr = rowBase + row;
        float a0 = sW4[768], a1 = sW4[769], a2 = sW4[770];
        const uint4* h4 = (const uint4*)(sA1 + row * SA);
        #pragma unroll
        for (int q = 0; q < 32; q++) {
            uint4 u = h4[q];
            const __nv_bfloat162* p = (const __nv_bfloat162*)&u;
            #pragma unroll
            for (int e = 0; e < 4; e++) {
                float2 hv = __bfloat1622float2(p[e]);
                int k = q * 8 + e * 2;
                a0 += hv.x * sW4[(k + 0) * 3 + 0];
                a1 += hv.x * sW4[(k + 0) * 3 + 1];
                a2 += hv.x * sW4[(k + 0) * 3 + 2];
                a0 += hv.y * sW4[(k + 1) * 3 + 0];
                a1 += hv.y * sW4[(k + 1) * 3 + 1];
                a2 += hv.y * sW4[(k + 1) * 3 + 2];
            }
        }
        if (gr < N) {
            out[3 * gr + 0] = 1.0f / (1.0f + expf(-a0));
            out[3 * gr + 1] = 1.0f / (1.0f + expf(-a1));
            out[3 * gr + 2] = 1.0f / (1.0f + expf(-a2));
        }
    }
}

// --------------------------------------------------------------- launcher ---
extern "C" void kernel_launch(void* const* d_in, const int* in_sizes, int n_in,
                              void* d_out, int out_size) {
    const float* x     = (const float*)d_in[0];
    const float* table = (const float*)d_in[1];
    const float* w1    = (const float*)d_in[2];
    const float* b1    = (const float*)d_in[3];
    const float* w2    = (const float*)d_in[4];
    const float* b2    = (const float*)d_in[5];
    const float* w3    = (const float*)d_in[6];
    const float* b3    = (const float*)d_in[7];
    const float* w4    = (const float*)d_in[8];
    const float* b4    = (const float*)d_in[9];
    float* out = (float*)d_out;

    int N = in_sizes[0] / 3;

    __nv_bfloat16 *featb, *w1b, *w2b, *w3b;
    cudaGetSymbolAddress((void**)&featb, g_featb);
    cudaGetSymbolAddress((void**)&w1b, g_w1b);
    cudaGetSymbolAddress((void**)&w2b, g_w2b);
    cudaGetSymbolAddress((void**)&w3b, g_w3b);

    cudaFuncSetAttribute(fused_mlp, cudaFuncAttributeMaxDynamicSharedMemorySize,
                         SMEM_BYTES);

    cvtw_kernel<<<256, 256>>>(w1, w2, w3, w1b, w2b, w3b);
    encode_kernel<<<(2 * N + 255) / 256, 256>>>(x, table, featb, N);
    fused_mlp<<<(N + 127) / 128, 256, SMEM_BYTES>>>(
        featb, w1b, w2b, w3b, b1, b2, b3, w4, b4, out, N);
}

// round 7
// speedup vs baseline: 1.0906x; 1.0906x over previous
#include <cuda_runtime.h>
#include <cuda_bf16.h>
#include <cstdint>

// ---------------- hash-grid constants (precomputed from reference config) ----
__constant__ float c_scale[16] = {
    15.0f,          21.1106061f,   29.5549331f,   41.2242532f,
    57.3502375f,    79.6349472f,  110.4304720f,  152.9872000f,
    211.7969070f,  293.0667790f,  405.3746690f,  560.5743900f,
    775.0469010f, 1071.4291820f, 1481.0036600f, 2047.0f
};
__constant__ uint32_t c_res1[5] = {17u, 24u, 32u, 44u, 60u};
__constant__ int c_offset[16] = {
    0, 4920, 18744, 51512, 136696, 352696, 876984, 1401272,
    1925560, 2449848, 2974136, 3498424, 4022712, 4547000, 5071288, 5595576
};

#define NPTS 524288

// bf16 weights (allocation-free rule: __device__ globals)
__device__ __nv_bfloat16 g_w1b[32 * 256];
__device__ __nv_bfloat16 g_w2b[256 * 256];
__device__ __nv_bfloat16 g_w3b[256 * 256];

// ------------------------------------------------------- weight conversion --
__global__ void cvtw_kernel(const float* __restrict__ w1,
                            const float* __restrict__ w2,
                            const float* __restrict__ w3,
                            __nv_bfloat16* __restrict__ o1,
                            __nv_bfloat16* __restrict__ o2,
                            __nv_bfloat16* __restrict__ o3) {
    int i = blockIdx.x * 256 + threadIdx.x;   // grid covers 65536
    if (i < 32 * 256) o1[i] = __float2bfloat16(w1[i]);
    o2[i] = __float2bfloat16(w2[i]);
    o3[i] = __float2bfloat16(w3[i]);
}

// ------------------------------------------------------------ PTX helpers ---
__device__ __forceinline__ uint32_t scvta(const void* p) {
    return (uint32_t)__cvta_generic_to_shared(p);
}
__device__ __forceinline__ void ldsm_x4(uint32_t* r, uint32_t addr) {
    asm volatile("ldmatrix.sync.aligned.m8n8.x4.shared.b16 {%0,%1,%2,%3}, [%4];"
                 : "=r"(r[0]), "=r"(r[1]), "=r"(r[2]), "=r"(r[3]) : "r"(addr));
}
__device__ __forceinline__ void ldsm_x4_t(uint32_t* r, uint32_t addr) {
    asm volatile("ldmatrix.sync.aligned.m8n8.x4.trans.shared.b16 {%0,%1,%2,%3}, [%4];"
                 : "=r"(r[0]), "=r"(r[1]), "=r"(r[2]), "=r"(r[3]) : "r"(addr));
}
__device__ __forceinline__ void mma_bf16(float* c, const uint32_t* a, const uint32_t* b) {
    asm volatile("mma.sync.aligned.m16n8k16.row.col.f32.bf16.bf16.f32 "
                 "{%0,%1,%2,%3}, {%4,%5,%6,%7}, {%8,%9}, {%0,%1,%2,%3};"
                 : "+f"(c[0]), "+f"(c[1]), "+f"(c[2]), "+f"(c[3])
                 : "r"(a[0]), "r"(a[1]), "r"(a[2]), "r"(a[3]),
                   "r"(b[0]), "r"(b[1]));
}
__device__ __forceinline__ void cp16(uint32_t smem, const void* gmem) {
    asm volatile("cp.async.cg.shared.global [%0], [%1], 16;"
                 :: "r"(smem), "l"(gmem));
}
__device__ __forceinline__ void cp_commit() {
    asm volatile("cp.async.commit_group;");
}
template <int NG>
__device__ __forceinline__ void cp_wait() {
    asm volatile("cp.async.wait_group %0;" :: "n"(NG));
}

// -------------------------------------------------------------- SMEM map ----
// per-CTA: A0 | A1 | W chunk | bias | w4   (two CTAs per SM)
#define SA   264                         // A row stride (bf16), conflict-free
#define SWS  136                         // W row stride (bf16), conflict-free
#define A_BYTES   (64 * SA * 2)          // 33792
#define W_BYTES   (128 * SWS * 2)        // 34816
#define A0_OFF    0
#define A1_OFF    A_BYTES
#define W_OFF     (2 * A_BYTES)
#define BIAS_OFF  (W_OFF + W_BYTES)      // float[768]
#define W4_OFF    (BIAS_OFF + 768 * 4)   // float[772]
#define SMEM_BYTES (W4_OFF + 772 * 4)    // 108560

// One layer: sOut[64,256] = relu(sIn[64,K] @ W[K,256] + bias), bf16 in/out.
// 8 warps = 2(M:32) x 4(N:32); 2 column passes of 128; K chunked by <=128.
template <int K>
__device__ __forceinline__ void layer64(const __nv_bfloat16* __restrict__ Wg,
                                        const float* sB,
                                        uint32_t sIn, __nv_bfloat16* sOutP,
                                        uint32_t sW, uint32_t sWsm) {
    constexpr int RCH = (K > 128) ? 128 : K;
    constexpr int NCH = K / RCH;

    const int tid  = threadIdx.x;
    const int lane = tid & 31;
    const int wid  = tid >> 5;
    const int m0   = (wid & 1) * 32;
    const int n0   = (wid >> 1) * 32;
    const int lr   = lane & 15;
    const int lc   = (lane >> 4) << 3;

    #pragma unroll
    for (int pass = 0; pass < 2; pass++) {
        const int colBase = pass * 128;

        float acc[2][4][4];
        #pragma unroll
        for (int mi = 0; mi < 2; mi++)
            #pragma unroll
            for (int nj = 0; nj < 4; nj++)
                #pragma unroll
                for (int q = 0; q < 4; q++) acc[mi][nj][q] = 0.0f;

        #pragma unroll
        for (int c = 0; c < NCH; c++) {
            __syncthreads();   // previous consumers of sW done / sIn ready
            // load W rows [c*RCH, +RCH), cols [colBase, +128)
            #pragma unroll
            for (int v = tid; v < RCH * 16; v += 256) {
                int r = v >> 4, c8 = (v & 15) * 8;
                cp16(sWsm + (r * SWS + c8) * 2,
                     Wg + (size_t)(c * RCH + r) * 256 + colBase + c8);
            }
            cp_commit();
            cp_wait<0>();
            __syncthreads();

            #pragma unroll
            for (int k0 = 0; k0 < RCH; k0 += 16) {
                const int kg = c * RCH + k0;
                uint32_t afr[2][4];
                #pragma unroll
                for (int mi = 0; mi < 2; mi++)
                    ldsm_x4(afr[mi], sIn + ((m0 + mi * 16 + lr) * SA + kg + lc) * 2);
                uint32_t bfr[4][2];
                #pragma unroll
                for (int nq = 0; nq < 2; nq++) {
                    uint32_t r[4];
                    ldsm_x4_t(r, sW + ((k0 + lr) * SWS + n0 + nq * 16 + lc) * 2);
                    bfr[nq * 2 + 0][0] = r[0]; bfr[nq * 2 + 0][1] = r[1];
                    bfr[nq * 2 + 1][0] = r[2]; bfr[nq * 2 + 1][1] = r[3];
                }
                #pragma unroll
                for (int mi = 0; mi < 2; mi++)
                    #pragma unroll
                    for (int nj = 0; nj < 4; nj++)
                        mma_bf16(acc[mi][nj], afr[mi], bfr[nj]);
            }
        }

        // bias + relu + store bf16x2 into sOut
        #pragma unroll
        for (int mi = 0; mi < 2; mi++) {
            #pragma unroll
            for (int nj = 0; nj < 4; nj++) {
                int colL = n0 + nj * 8 + (lane & 3) * 2;
                float b0v = sB[colBase + colL], b1v = sB[colBase + colL + 1];
                int row = m0 + mi * 16 + (lane >> 2);
                float v0 = fmaxf(acc[mi][nj][0] + b0v, 0.0f);
                float v1 = fmaxf(acc[mi][nj][1] + b1v, 0.0f);
                *(__nv_bfloat162*)(sOutP + row * SA + colBase + colL) =
                    __float22bfloat162_rn(make_float2(v0, v1));
                float v2 = fmaxf(acc[mi][nj][2] + b0v, 0.0f);
                float v3 = fmaxf(acc[mi][nj][3] + b1v, 0.0f);
                *(__nv_bfloat162*)(sOutP + (row + 8) * SA + colBase + colL) =
                    __float22bfloat162_rn(make_float2(v2, v3));
            }
        }
    }
}

// --------------------------------- fused encode + MLP, 64 pts/block, occ 2 --
__global__ void __launch_bounds__(256, 2)
fused_all(const float* __restrict__ x,
          const float* __restrict__ table,
          const __nv_bfloat16* __restrict__ w1b,
          const __nv_bfloat16* __restrict__ w2b,
          const __nv_bfloat16* __restrict__ w3b,
          const float* __restrict__ b1, const float* __restrict__ b2,
          const float* __restrict__ b3, const float* __restrict__ w4,
          const float* __restrict__ b4, float* __restrict__ out, int N) {
    extern __shared__ char smem[];
    const uint32_t sb = scvta(smem);
    __nv_bfloat16* sA0p = (__nv_bfloat16*)(smem + A0_OFF);
    __nv_bfloat16* sA1p = (__nv_bfloat16*)(smem + A1_OFF);
    float* sBias = (float*)(smem + BIAS_OFF);
    float* sW4   = (float*)(smem + W4_OFF);

    const int tid = threadIdx.x;
    const int rowBase = blockIdx.x * 64;

    // ---- preload biases + final weights ----
    sBias[tid]       = b1[tid];
    sBias[256 + tid] = b2[tid];
    sBias[512 + tid] = b3[tid];
    for (int v = tid; v < 771; v += 256) sW4[v] = (v < 768) ? w4[v] : b4[v - 768];

    // ---- encode: 4 threads per point, 4 levels each, straight into sA0 ----
    {
        const int p  = tid >> 2;
        const int lg = tid & 3;
        const int gp = min(rowBase + p, N - 1);
        float x0 = __ldg(x + 3 * gp + 0) * (1.0f / 1.5f);
        float x1 = __ldg(x + 3 * gp + 1) * (1.0f / 1.5f);
        float x2 = __ldg(x + 3 * gp + 2) * (1.0f / 1.5f);

        #pragma unroll
        for (int li = 0; li < 4; li++) {
            const int l = lg * 4 + li;
            float s = c_scale[l];
            float px = x0 * s + 0.5f;
            float py = x1 * s + 0.5f;
            float pz = x2 * s + 0.5f;
            float fx = floorf(px), fy = floorf(py), fz = floorf(pz);
            float tx = px - fx, ty = py - fy, tz = pz - fz;
            uint32_t X = (uint32_t)fx, Y = (uint32_t)fy, Z = (uint32_t)fz;
            float wx[2] = {1.0f - tx, tx};
            float wy[2] = {1.0f - ty, ty};
            float wz[2] = {1.0f - tz, tz};

            float a0 = 0.0f, a1 = 0.0f;
            #pragma unroll
            for (int cc = 0; cc < 8; cc++) {
                uint32_t bx = (uint32_t)(cc & 1);
                uint32_t by = (uint32_t)((cc >> 1) & 1);
                uint32_t bz = (uint32_t)((cc >> 2) & 1);
                uint32_t cx = X + bx, cy = Y + by, cz = Z + bz;
                uint32_t idx;
                if (l < 5) {
                    uint32_t r1 = c_res1[l];
                    idx = cx + cy * r1 + cz * r1 * r1;   // dense
                } else {
                    idx = (cx * 1u ^ cy * 2654435761u ^ cz * 805459861u) & 524287u;
                }
                float w = wx[bx] * wy[by] * wz[bz];
                float2 t2 = __ldg((const float2*)table + (c_offset[l] + (int)idx));
                a0 += w * t2.x;
                a1 += w * t2.y;
            }
            *(__nv_bfloat162*)(sA0p + p * SA + 2 * l) =
                __float22bfloat162_rn(make_float2(a0, a1));
        }
    }
    // (layer64's first __syncthreads orders encode stores before MMA reads)

    layer64<32>(w1b, sBias,        sb + A0_OFF, sA1p, sb + W_OFF, sb + W_OFF);
    layer64<256>(w2b, sBias + 256, sb + A1_OFF, sA0p, sb + W_OFF, sb + W_OFF);
    layer64<256>(w3b, sBias + 512, sb + A0_OFF, sA1p, sb + W_OFF, sb + W_OFF);
    __syncthreads();

    // ---- final layer: 4 threads per point, 64 cols each, shuffle reduce ----
    {
        const int p = tid >> 2;
        const int q = tid & 3;
        const int gr = rowBase + p;
        float a0 = 0.0f, a1 = 0.0f, a2 = 0.0f;
        const uint4* h4 = (const uint4*)(sA1p + p * SA + q * 64);
        #pragma unroll
        for (int j = 0; j < 8; j++) {
            uint4 u = h4[j];
            const __nv_bfloat162* pr = (const __nv_bfloat162*)&u;
            #pragma unroll
            for (int e = 0; e < 4; e++) {
                float2 hv = __bfloat1622float2(pr[e]);
                int k = q * 64 + j * 8 + e * 2;
                a0 += hv.x * sW4[(k + 0) * 3 + 0];
                a1 += hv.x * sW4[(k + 0) * 3 + 1];
                a2 += hv.x * sW4[(k + 0) * 3 + 2];
                a0 += hv.y * sW4[(k + 1) * 3 + 0];
                a1 += hv.y * sW4[(k + 1) * 3 + 1];
                a2 += hv.y * sW4[(k + 1) * 3 + 2];
            }
        }
        a0 += __shfl_xor_sync(0xFFFFFFFFu, a0, 1);
        a1 += __shfl_xor_sync(0xFFFFFFFFu, a1, 1);
        a2 += __shfl_xor_sync(0xFFFFFFFFu, a2, 1);
        a0 += __shfl_xor_sync(0xFFFFFFFFu, a0, 2);
        a1 += __shfl_xor_sync(0xFFFFFFFFu, a1, 2);
        a2 += __shfl_xor_sync(0xFFFFFFFFu, a2, 2);
        if (q == 0 && gr < N) {
            a0 += sW4[768]; a1 += sW4[769]; a2 += sW4[770];
            out[3 * gr + 0] = 1.0f / (1.0f + expf(-a0));
            out[3 * gr + 1] = 1.0f / (1.0f + expf(-a1));
            out[3 * gr + 2] = 1.0f / (1.0f + expf(-a2));
        }
    }
}

// --------------------------------------------------------------- launcher ---
extern "C" void kernel_launch(void* const* d_in, const int* in_sizes, int n_in,
                              void* d_out, int out_size) {
    const float* x     = (const float*)d_in[0];
    const float* table = (const float*)d_in[1];
    const float* w1    = (const float*)d_in[2];
    const float* b1    = (const float*)d_in[3];
    const float* w2    = (const float*)d_in[4];
    const float* b2    = (const float*)d_in[5];
    const float* w3    = (const float*)d_in[6];
    const float* b3    = (const float*)d_in[7];
    const float* w4    = (const float*)d_in[8];
    const float* b4    = (const float*)d_in[9];
    float* out = (float*)d_out;

    int N = in_sizes[0] / 3;

    __nv_bfloat16 *w1b, *w2b, *w3b;
    cudaGetSymbolAddress((void**)&w1b, g_w1b);
    cudaGetSymbolAddress((void**)&w2b, g_w2b);
    cudaGetSymbolAddress((void**)&w3b, g_w3b);

    cudaFuncSetAttribute(fused_all, cudaFuncAttributeMaxDynamicSharedMemorySize,
                         SMEM_BYTES);

    cvtw_kernel<<<256, 256>>>(w1, w2, w3, w1b, w2b, w3b);
    fused_all<<<(N + 63) / 64, 256, SMEM_BYTES>>>(
        x, table, w1b, w2b, w3b, b1, b2, b3, w4, b4, out, N);
}

// round 10
// speedup vs baseline: 1.7740x; 1.6267x over previous
#include <cuda_runtime.h>
#include <cuda_bf16.h>
#include <cstdint>

// ---------------- hash-grid constants (precomputed from reference config) ----
__constant__ float c_scale[16] = {
    15.0f,          21.1106061f,   29.5549331f,   41.2242532f,
    57.3502375f,    79.6349472f,  110.4304720f,  152.9872000f,
    211.7969070f,  293.0667790f,  405.3746690f,  560.5743900f,
    775.0469010f, 1071.4291820f, 1481.0036600f, 2047.0f
};
__constant__ uint32_t c_res1[5] = {17u, 24u, 32u, 44u, 60u};
__constant__ int c_offset[16] = {
    0, 4920, 18744, 51512, 136696, 352696, 876984, 1401272,
    1925560, 2449848, 2974136, 3498424, 4022712, 4547000, 5071288, 5595576
};

// W chunk stream: 12 chunks (L1 c0..3, L2 c0..3, L3 c0..3), each the exact
// smem image: rows = K, 64 cols + 8 pad (stride 72 bf16 = 144 B), flat.
__constant__ uint32_t c_chunk_off[12] = {
    0u, 4608u, 9216u, 13824u,
    18432u, 55296u, 92160u, 129024u,
    165888u, 202752u, 239616u, 276480u
};
__constant__ uint32_t c_chunk_bytes[12] = {
    4608u, 4608u, 4608u, 4608u,
    36864u, 36864u, 36864u, 36864u,
    36864u, 36864u, 36864u, 36864u
};

#define NPTS 524288

// pre-baked weight chunk blob (allocation-free rule: __device__ global)
__device__ char g_wblob[313344];

// ------------------------------------------------------- weight baking ------
// chunk image: for chunk (layer, nc): elem (k, n) at k*72 + (n - nc*64), bf16
__global__ void cvtw_kernel(const float* __restrict__ w1,
                            const float* __restrict__ w2,
                            const float* __restrict__ w3,
                            char* __restrict__ blob) {
    int i = blockIdx.x * 256 + threadIdx.x;   // i = k*256 + n, 65536 total
    int k = i >> 8, n = i & 255;
    uint32_t nc = (uint32_t)(n >> 6);
    uint32_t eoff = ((uint32_t)k * 72u + (uint32_t)(n & 63)) * 2u;
    *(__nv_bfloat16*)(blob + 18432u + nc * 36864u + eoff) = __float2bfloat16(w2[i]);
    *(__nv_bfloat16*)(blob + 165888u + nc * 36864u + eoff) = __float2bfloat16(w3[i]);
    if (k < 32)
        *(__nv_bfloat16*)(blob + nc * 4608u + eoff) = __float2bfloat16(w1[i]);
}

// ------------------------------------------------------------ PTX helpers ---
__device__ __forceinline__ uint32_t scvta(const void* p) {
    return (uint32_t)__cvta_generic_to_shared(p);
}
__device__ __forceinline__ void ldsm_x4(uint32_t* r, uint32_t addr) {
    asm volatile("ldmatrix.sync.aligned.m8n8.x4.shared.b16 {%0,%1,%2,%3}, [%4];"
                 : "=r"(r[0]), "=r"(r[1]), "=r"(r[2]), "=r"(r[3]) : "r"(addr));
}
__device__ __forceinline__ void ldsm_x4_t(uint32_t* r, uint32_t addr) {
    asm volatile("ldmatrix.sync.aligned.m8n8.x4.trans.shared.b16 {%0,%1,%2,%3}, [%4];"
                 : "=r"(r[0]), "=r"(r[1]), "=r"(r[2]), "=r"(r[3]) : "r"(addr));
}
__device__ __forceinline__ void mma_bf16(float* c, const uint32_t* a, const uint32_t* b) {
    asm volatile("mma.sync.aligned.m16n8k16.row.col.f32.bf16.bf16.f32 "
                 "{%0,%1,%2,%3}, {%4,%5,%6,%7}, {%8,%9}, {%0,%1,%2,%3};"
                 : "+f"(c[0]), "+f"(c[1]), "+f"(c[2]), "+f"(c[3])
                 : "r"(a[0]), "r"(a[1]), "r"(a[2]), "r"(a[3]),
                   "r"(b[0]), "r"(b[1]));
}
__device__ __forceinline__ void cp16(uint32_t smem, const void* gmem) {
    asm volatile("cp.async.cg.shared.global [%0], [%1], 16;"
                 :: "r"(smem), "l"(gmem));
}
__device__ __forceinline__ void cp_commit() {
    asm volatile("cp.async.commit_group;");
}
template <int NG>
__device__ __forceinline__ void cp_wait() {
    asm volatile("cp.async.wait_group %0;" :: "n"(NG));
}
__device__ __forceinline__ uint32_t packrelu(float a, float b) {
    __nv_bfloat162 t = __float22bfloat162_rn(
        make_float2(fmaxf(a, 0.0f), fmaxf(b, 0.0f)));
    return *(uint32_t*)&t;
}

// -------------------------------------------------------------- SMEM map ----
#define WSLOT     36864
#define W_OFF     0
#define FEAT_OFF  (2 * WSLOT)                 // 73728 : 128 x 40 bf16
#define SF        40
#define BIAS_OFF  (FEAT_OFF + 128 * SF * 2)   // 83968 : float[768] b1|b2|b3
#define W4_OFF    (BIAS_OFF + 768 * 4)        // 87040 : float[772] w4|b4
#define SMEM_BYTES (W4_OFF + 772 * 4)         // 90128

// issue cp.async for chunk s into its ring slot (slot = s & 1)
__device__ __forceinline__ void issue_chunk(uint32_t sb, const char* blob,
                                            int s, int tid) {
    uint32_t dst = sb + W_OFF + (uint32_t)(s & 1) * WSLOT;
    uint32_t off = c_chunk_off[s];
    uint32_t bytes = c_chunk_bytes[s];
    for (uint32_t o = (uint32_t)tid * 16u; o < bytes; o += 4096u)
        cp16(dst + o, blob + off + o);
    cp_commit();
}

// MMA over one W chunk (64 cols), KB = K/16 kblocks. acc[8][4] += A*W.
template <int KB>
__device__ __forceinline__ void chunk_mma(uint32_t sW, int lr2, int lc2,
                                          const uint32_t (*aF)[4],
                                          float (*acc)[4]) {
    #pragma unroll
    for (int kb = 0; kb < KB; kb++) {
        uint32_t bt[4][4];
        #pragma unroll
        for (int nq = 0; nq < 4; nq++)
            ldsm_x4_t(bt[nq], sW + (uint32_t)(((kb * 16 + lr2) * 72
                                               + nq * 16 + lc2) * 2));
        #pragma unroll
        for (int nq = 0; nq < 4; nq++) {
            mma_bf16(acc[2 * nq],     aF[kb], &bt[nq][0]);
            mma_bf16(acc[2 * nq + 1], aF[kb], &bt[nq][2]);
        }
    }
}

// bias + relu + C-frag -> next-layer A-frag (bf16) for 4 kblocks (64 cols)
__device__ __forceinline__ void epi_build(const float (*acc)[4],
                                          const float* sB, int colBase,
                                          int l2x, uint32_t (*outA)[4]) {
    #pragma unroll
    for (int t = 0; t < 4; t++) {
        float b00 = sB[colBase + 16 * t + l2x];
        float b01 = sB[colBase + 16 * t + l2x + 1];
        float b10 = sB[colBase + 16 * t + 8 + l2x];
        float b11 = sB[colBase + 16 * t + 8 + l2x + 1];
        const float* cA = acc[2 * t];
        const float* cB = acc[2 * t + 1];
        outA[t][0] = packrelu(cA[0] + b00, cA[1] + b01);
        outA[t][1] = packrelu(cA[2] + b00, cA[3] + b01);
        outA[t][2] = packrelu(cB[0] + b10, cB[1] + b11);
        outA[t][3] = packrelu(cB[2] + b10, cB[3] + b11);
    }
}

// --------------------------------- fused encode + register-resident MLP -----
__global__ void __launch_bounds__(256)
fused_all(const float* __restrict__ x,
          const float* __restrict__ table,
          const char* __restrict__ blob,
          const float* __restrict__ b1, const float* __restrict__ b2,
          const float* __restrict__ b3, const float* __restrict__ w4,
          const float* __restrict__ b4, float* __restrict__ out, int N) {
    extern __shared__ char smem[];
    const uint32_t sb = scvta(smem);
    __nv_bfloat16* sFeat = (__nv_bfloat16*)(smem + FEAT_OFF);
    float* sBias = (float*)(smem + BIAS_OFF);
    float* sW4   = (float*)(smem + W4_OFF);

    const int tid = threadIdx.x;
    const int lane = tid & 31;
    const int wid = tid >> 5;
    const int m0 = wid * 16;
    const int lr2 = lane & 15;
    const int lc2 = (lane >> 4) << 3;
    const int l2x = (lane & 3) * 2;
    const int rowBase = blockIdx.x * 128;

    // kick off W1 chunks 0,1 immediately (overlaps encode)
    issue_chunk(sb, blob, 0, tid);
    issue_chunk(sb, blob, 1, tid);

    // ---- biases + final weights ----
    sBias[tid]       = b1[tid];
    sBias[256 + tid] = b2[tid];
    sBias[512 + tid] = b3[tid];
    for (int v = tid; v < 771; v += 256) sW4[v] = (v < 768) ? w4[v] : b4[v - 768];

    // ---- encode: 2 threads per point, 8 levels each -> feat smem ----
    {
        const int p = tid >> 1;
        const int h = tid & 1;
        const int gp = min(rowBase + p, N - 1);
        float x0 = __ldg(x + 3 * gp + 0) * (1.0f / 1.5f);
        float x1 = __ldg(x + 3 * gp + 1) * (1.0f / 1.5f);
        float x2 = __ldg(x + 3 * gp + 2) * (1.0f / 1.5f);

        #pragma unroll
        for (int li = 0; li < 8; li++) {
            const int l = h * 8 + li;
            float s = c_scale[l];
            float px = x0 * s + 0.5f;
            float py = x1 * s + 0.5f;
            float pz = x2 * s + 0.5f;
            float fx = floorf(px), fy = floorf(py), fz = floorf(pz);
            float tx = px - fx, ty = py - fy, tz = pz - fz;
            uint32_t X = (uint32_t)fx, Y = (uint32_t)fy, Z = (uint32_t)fz;
            float wx[2] = {1.0f - tx, tx};
            float wy[2] = {1.0f - ty, ty};
            float wz[2] = {1.0f - tz, tz};

            float a0 = 0.0f, a1 = 0.0f;
            #pragma unroll
            for (int cc = 0; cc < 8; cc++) {
                uint32_t bx = (uint32_t)(cc & 1);
                uint32_t by = (uint32_t)((cc >> 1) & 1);
                uint32_t bz = (uint32_t)((cc >> 2) & 1);
                uint32_t cx = X + bx, cy = Y + by, cz = Z + bz;
                uint32_t idx;
                if (h == 0 && li < 5) {
                    uint32_t r1 = c_res1[li];
                    idx = cx + cy * r1 + cz * r1 * r1;   // dense
                } else {
                    idx = (cx * 1u ^ cy * 2654435761u ^ cz * 805459861u) & 524287u;
                }
                float w = wx[bx] * wy[by] * wz[bz];
                float2 t2 = __ldg((const float2*)table + (c_offset[l] + (int)idx));
                a0 += w * t2.x;
                a1 += w * t2.y;
            }
            *(__nv_bfloat162*)(sFeat + p * SF + 2 * l) =
                __float22bfloat162_rn(make_float2(a0, a1));
        }
    }
    __syncthreads();   // feat visible to all warps

    // A fragments for layer 1 (K=32 -> 2 kblocks); rows m0..m0+15
    uint32_t a1f[2][4];
    #pragma unroll
    for (int kb = 0; kb < 2; kb++)
        ldsm_x4(a1f[kb], sb + FEAT_OFF
                + (uint32_t)(((m0 + lr2) * SF + kb * 16 + lc2) * 2));

    uint32_t a2f[16][4];
    uint32_t a3f[16][4];
    float p0[3] = {0.0f, 0.0f, 0.0f};
    float p1[3] = {0.0f, 0.0f, 0.0f};

    // ================= LAYER 1 (K=32, chunks s=0..3) =================
    #pragma unroll
    for (int c = 0; c < 4; c++) {
        const int s = c;
        cp_wait<1>();      // chunk s resident (one group still in flight)
        __syncthreads();
        uint32_t sW = sb + W_OFF + (uint32_t)(s & 1) * WSLOT;
        float acc[8][4];
        #pragma unroll
        for (int j = 0; j < 8; j++)
            #pragma unroll
            for (int q = 0; q < 4; q++) acc[j][q] = 0.0f;
        chunk_mma<2>(sW, lr2, lc2, a1f, acc);
        epi_build(acc, sBias, c * 64, l2x, &a2f[4 * c]);
        __syncthreads();   // all warps done reading slot (s&1)
        issue_chunk(sb, blob, s + 2, tid);
    }

    // ================= LAYER 2 (K=256, chunks s=4..7) =================
    #pragma unroll
    for (int c = 0; c < 4; c++) {
        const int s = 4 + c;
        cp_wait<1>();
        __syncthreads();
        uint32_t sW = sb + W_OFF + (uint32_t)(s & 1) * WSLOT;
        float acc[8][4];
        #pragma unroll
        for (int j = 0; j < 8; j++)
            #pragma unroll
            for (int q = 0; q < 4; q++) acc[j][q] = 0.0f;
        chunk_mma<16>(sW, lr2, lc2, a2f, acc);
        epi_build(acc, sBias + 256, c * 64, l2x, &a3f[4 * c]);
        __syncthreads();
        issue_chunk(sb, blob, s + 2, tid);
    }

    // ================= LAYER 3 (K=256, chunks s=8..11) + final ==========
    #pragma unroll
    for (int c = 0; c < 4; c++) {
        if (c < 3) { cp_wait<1>(); } else { cp_wait<0>(); }
        __syncthreads();
        const int s = 8 + c;
        uint32_t sW = sb + W_OFF + (uint32_t)(s & 1) * WSLOT;
        float acc[8][4];
        #pragma unroll
        for (int j = 0; j < 8; j++)
            #pragma unroll
            for (int q = 0; q < 4; q++) acc[j][q] = 0.0f;
        chunk_mma<16>(sW, lr2, lc2, a3f, acc);
        if (c < 2) {
            __syncthreads();   // done reading slot before next issue overwrites
            issue_chunk(sb, blob, s + 2, tid);
        }
        // fused final layer: relu then dot with w4 columns (cols c*64..+63)
        const float* sB3 = sBias + 512;
        #pragma unroll
        for (int t = 0; t < 8; t++) {
            int col0 = c * 64 + t * 8 + l2x;
            float b0v = sB3[col0], b1v = sB3[col0 + 1];
            float v0 = fmaxf(acc[t][0] + b0v, 0.0f);
            float v1 = fmaxf(acc[t][1] + b1v, 0.0f);
            float v2 = fmaxf(acc[t][2] + b0v, 0.0f);
            float v3 = fmaxf(acc[t][3] + b1v, 0.0f);
            #pragma unroll
            for (int j = 0; j < 3; j++) {
                float w0 = sW4[col0 * 3 + j], w1v = sW4[(col0 + 1) * 3 + j];
                p0[j] += v0 * w0 + v1 * w1v;
                p1[j] += v2 * w0 + v3 * w1v;
            }
        }
    }

    // ---- quad reduce (lanes of one row differ in bits 0,1 of lane id) ----
    #pragma unroll
    for (int j = 0; j < 3; j++) {
        p0[j] += __shfl_xor_sync(0xFFFFFFFFu, p0[j], 1);
        p1[j] += __shfl_xor_sync(0xFFFFFFFFu, p1[j], 1);
        p0[j] += __shfl_xor_sync(0xFFFFFFFFu, p0[j], 2);
        p1[j] += __shfl_xor_sync(0xFFFFFFFFu, p1[j], 2);
    }
    if ((lane & 3) == 0) {
        int r0 = rowBase + m0 + (lane >> 2);
        int r1 = r0 + 8;
        if (r0 < N) {
            #pragma unroll
            for (int j = 0; j < 3; j++)
                out[3 * r0 + j] = 1.0f / (1.0f + expf(-(p0[j] + sW4[768 + j])));
        }
        if (r1 < N) {
            #pragma unroll
            for (int j = 0; j < 3; j++)
                out[3 * r1 + j] = 1.0f / (1.0f + expf(-(p1[j] + sW4[768 + j])));
        }
    }
}

// --------------------------------------------------------------- launcher ---
extern "C" void kernel_launch(void* const* d_in, const int* in_sizes, int n_in,
                              void* d_out, int out_size) {
    const float* x     = (const float*)d_in[0];
    const float* table = (const float*)d_in[1];
    const float* w1    = (const float*)d_in[2];
    const float* b1    = (const float*)d_in[3];
    const float* w2    = (const float*)d_in[4];
    const float* b2    = (const float*)d_in[5];
    const float* w3    = (const float*)d_in[6];
    const float* b3    = (const float*)d_in[7];
    const float* w4    = (const float*)d_in[8];
    const float* b4    = (const float*)d_in[9];
    float* out = (float*)d_out;

    int N = in_sizes[0] / 3;

    char* blob;
    cudaGetSymbolAddress((void**)&blob, g_wblob);

    cudaFuncSetAttribute(fused_all, cudaFuncAttributeMaxDynamicSharedMemorySize,
                         SMEM_BYTES);

    cvtw_kernel<<<256, 256>>>(w1, w2, w3, blob);
    fused_all<<<(N + 127) / 128, 256, SMEM_BYTES>>>(
        x, table, blob, b1, b2, b3, w4, b4, out, N);
}